// round 8
// baseline (speedup 1.0000x reference)
#include <cuda_runtime.h>
#include <cuda_bf16.h>
#include <mma.h>
#include <cstdint>

using namespace nvcuda;

// Problem constants (fixed by the dataset)
#define NN 40000
#define EE 400000
#define GG 256
#define DIN 256
#define DHC 128      // channels per head
#define HH 4

#define MPAD 40192   // 157 * 256, padded rows for unguarded tensor-core stores

// ---------------- scratch (static device globals; no allocation) ----------------
__device__ float g_hlin[(size_t)MPAD * 512];   // linear output of current layer (padded)
__device__ float g_xtf[(size_t)NN * DIN];      // tf32-rounded input features
__device__ float g_w1t[DIN * 512];             // tf32-rounded weights
__device__ float g_w2t[128 * 512];
__device__ float g_w3t[128 * 128];
__device__ float g_f1[(size_t)NN * 128];       // layer1 out (tf32-rounded)
__device__ float g_f2[(size_t)NN * 128];       // layer2 out (tf32-rounded)
__device__ float g_f3[(size_t)NN * 128];       // layer3 out
__device__ float g_ssrc[NN * HH];
__device__ float g_sdst[NN * HH];
__device__ int   g_rowptr[NN + 1];
__device__ int   g_cursor[NN];
__device__ int   g_deg[NN];
__device__ int   g_esrc[EE];
__device__ int   g_bsums[64];
__device__ float g_tot[GG * 128];
__device__ float g_cnt[GG];

__device__ __forceinline__ float rtf32(float x) { return wmma::__float_to_tf32(x); }

// ---------------- utility kernels ----------------
__global__ void kzero_i(int* p, int n) {
    int i = blockIdx.x * blockDim.x + threadIdx.x;
    if (i < n) p[i] = 0;
}
// zero tot (GG*128) and cnt (GG) in one launch
__global__ void kzero_pool(float* tot, float* cnt) {
    int i = blockIdx.x * blockDim.x + threadIdx.x;
    if (i < GG * 128) tot[i] = 0.f;
    if (i < GG) cnt[i] = 0.f;
}

// round float array to tf32 (float4-vectorized; n % 4 == 0)
__global__ void round_tf32(const float* __restrict__ in, float* __restrict__ out, int n4) {
    int i = blockIdx.x * blockDim.x + threadIdx.x;
    if (i < n4) {
        float4 v = ((const float4*)in)[i];
        v.x = rtf32(v.x); v.y = rtf32(v.y); v.z = rtf32(v.z); v.w = rtf32(v.w);
        ((float4*)out)[i] = v;
    }
}

__global__ void hist_k(const int* __restrict__ dst, int* __restrict__ deg) {
    int e = blockIdx.x * blockDim.x + threadIdx.x;
    if (e < EE) atomicAdd(&deg[dst[e]], 1);
}

// block-wise exclusive scan (1024 per block) + block totals
__global__ void scan_block(const int* __restrict__ deg, int* __restrict__ rowptr,
                           int* __restrict__ bsums, int n) {
    __shared__ int tmp[1024];
    int i = blockIdx.x * 1024 + threadIdx.x;
    int v = (i < n) ? deg[i] : 0;
    tmp[threadIdx.x] = v;
    __syncthreads();
    for (int off = 1; off < 1024; off <<= 1) {
        int t = (threadIdx.x >= off) ? tmp[threadIdx.x - off] : 0;
        __syncthreads();
        tmp[threadIdx.x] += t;
        __syncthreads();
    }
    if (i < n) rowptr[i] = tmp[threadIdx.x] - v;  // exclusive
    if (threadIdx.x == 1023) bsums[blockIdx.x] = tmp[1023];
}

__global__ void scan_sums(int* bsums, int nb) {
    if (threadIdx.x == 0 && blockIdx.x == 0) {
        int run = 0;
        for (int b = 0; b < nb; b++) { int v = bsums[b]; bsums[b] = run; run += v; }
    }
}

__global__ void scan_add(int* __restrict__ rowptr, int* __restrict__ cursor,
                         const int* __restrict__ bsums, int n) {
    int i = blockIdx.x * blockDim.x + threadIdx.x;
    if (i < n) {
        int v = rowptr[i] + bsums[i >> 10];
        rowptr[i] = v;
        cursor[i] = v;
    }
    if (i == 0) rowptr[n] = EE;
}

__global__ void scatter_k(const int* __restrict__ src, const int* __restrict__ dst,
                          int* __restrict__ cursor, int* __restrict__ esrc) {
    int e = blockIdx.x * blockDim.x + threadIdx.x;
    if (e < EE) {
        int pos = atomicAdd(&cursor[dst[e]], 1);
        esrc[pos] = src[e];
    }
}

// ---------------- TF32 tensor-core GEMM, cp.async double-buffered ----------------
// C[M,Nc] = A[M,K] @ B[K,Nc]. A and B must be PRE-ROUNDED to tf32 values.
// Block tile 256x128, BK=16, 8 warps (4M x 2N), warp tile 64x64 = 4x4 wmma
// 16x16x8 tf32 (16 MMAs per 8 fragment loads). K % 16 == 0, Nc % 128 == 0.
// C rows padded to 256 (MPAD) so stores are unguarded; A rows guarded by
// cp.async zero-size fill. 57KB dynamic smem.
#define GBM 256
#define GBN 128
#define GBK 16
#define GLDA 20    // 16 + 4 pad (floats)
#define GLDB 132   // 128 + 4 pad (floats)
#define GEMM_SMEM ((2 * GBM * GLDA + 2 * GBK * GLDB) * 4)

__global__ __launch_bounds__(256, 1) void gemm_tf32(int M, int K, int Nc,
    const float* __restrict__ A, const float* __restrict__ B, float* __restrict__ C)
{
    extern __shared__ float smem[];
    float* As = smem;                      // [2][GBM*GLDA]
    float* Bs = smem + 2 * GBM * GLDA;     // [2][GBK*GLDB]

    const int tid = threadIdx.x;
    const int warpId = tid >> 5;
    const int warpM = warpId & 3;      // M offset warpM*64
    const int warpN = warpId >> 2;     // N offset warpN*64
    const int blockM = blockIdx.y * GBM;
    const int blockN = blockIdx.x * GBN;

    const unsigned int sA = (unsigned int)__cvta_generic_to_shared(As);
    const unsigned int sB = (unsigned int)__cvta_generic_to_shared(Bs);

    wmma::fragment<wmma::accumulator, 16, 16, 8, float> acc[4][4];
#pragma unroll
    for (int i = 0; i < 4; i++)
#pragma unroll
        for (int j = 0; j < 4; j++) wmma::fill_fragment(acc[i][j], 0.f);

    const int nsteps = K / GBK;

    // --- staging: A = 1024 float4 chunks (4/thread), B = 512 (2/thread) ---
    auto stage = [&](int buf, int k0) {
#pragma unroll
        for (int q = 0; q < 4; q++) {
            int c = tid + q * 256;
            int ar = c >> 2, ac = (c & 3) * 4;
            int gr = blockM + ar;
            const float* gpA = A + (size_t)gr * K + k0 + ac;
            unsigned int saA = sA + (unsigned int)(buf * GBM * GLDA + ar * GLDA + ac) * 4u;
            int sz = (gr < M) ? 16 : 0;
            asm volatile("cp.async.cg.shared.global [%0], [%1], 16, %2;\n"
                         :: "r"(saA), "l"(gpA), "r"(sz));
        }
#pragma unroll
        for (int q = 0; q < 2; q++) {
            int c = tid + q * 256;
            int br = c >> 5, bc = (c & 31) * 4;
            const float* gpB = B + (size_t)(k0 + br) * Nc + blockN + bc;
            unsigned int saB = sB + (unsigned int)(buf * GBK * GLDB + br * GLDB + bc) * 4u;
            asm volatile("cp.async.cg.shared.global [%0], [%1], 16;\n"
                         :: "r"(saB), "l"(gpB));
        }
        asm volatile("cp.async.commit_group;\n");
    };

    stage(0, 0);

    for (int s = 0; s < nsteps; s++) {
        const int p = s & 1;
        if (s + 1 < nsteps) {
            stage(1 - p, (s + 1) * GBK);
            asm volatile("cp.async.wait_group 1;\n");
        } else {
            asm volatile("cp.async.wait_group 0;\n");
        }
        __syncthreads();

        const float* ap = As + p * GBM * GLDA;
        const float* bp = Bs + p * GBK * GLDB;
#pragma unroll
        for (int kk = 0; kk < GBK; kk += 8) {
            wmma::fragment<wmma::matrix_a, 16, 16, 8, wmma::precision::tf32, wmma::row_major> af[4];
            wmma::fragment<wmma::matrix_b, 16, 16, 8, wmma::precision::tf32, wmma::row_major> bf[4];
#pragma unroll
            for (int i = 0; i < 4; i++)
                wmma::load_matrix_sync(af[i], ap + (warpM * 64 + i * 16) * GLDA + kk, GLDA);
#pragma unroll
            for (int j = 0; j < 4; j++)
                wmma::load_matrix_sync(bf[j], bp + kk * GLDB + warpN * 64 + j * 16, GLDB);
#pragma unroll
            for (int i = 0; i < 4; i++)
#pragma unroll
                for (int j = 0; j < 4; j++)
                    wmma::mma_sync(acc[i][j], af[i], bf[j], acc[i][j]);
        }
        __syncthreads();
    }

#pragma unroll
    for (int i = 0; i < 4; i++)
#pragma unroll
        for (int j = 0; j < 4; j++) {
            size_t row = blockM + warpM * 64 + i * 16;
            wmma::store_matrix_sync(C + row * Nc + blockN + warpN * 64 + j * 16,
                                    acc[i][j], Nc, wmma::mem_row_major);
        }
}

// ---------------- attention scores: s_src[n,h], s_dst[n,h] ----------------
template <int HEADS>
__global__ void att_scores(const float* __restrict__ h, const float* __restrict__ asrc,
                           const float* __restrict__ adst, float* __restrict__ ssrc,
                           float* __restrict__ sdst)
{
    const int n = blockIdx.x;
    const int w = threadIdx.x >> 5;
    const int lane = threadIdx.x & 31;
    const float4 hv = *(const float4*)(h + (size_t)n * HEADS * 128 + w * 128 + lane * 4);
    const float4 av = *(const float4*)(asrc + w * 128 + lane * 4);
    const float4 dv = *(const float4*)(adst + w * 128 + lane * 4);
    float a = hv.x * av.x + hv.y * av.y + hv.z * av.z + hv.w * av.w;
    float d = hv.x * dv.x + hv.y * dv.y + hv.z * dv.z + hv.w * dv.w;
#pragma unroll
    for (int off = 16; off; off >>= 1) {
        a += __shfl_xor_sync(0xffffffffu, a, off);
        d += __shfl_xor_sync(0xffffffffu, d, off);
    }
    if (lane == 0) {
        ssrc[n * HEADS + w] = a;
        sdst[n * HEADS + w] = d;
    }
}

// ---------------- per-dst aggregation + epilogue ----------------
// ELUBN layers also round their outputs to tf32 (they feed the next GEMM).
template <int HEADS, bool ELUBN>
__global__ void gat_agg(const float* __restrict__ hlin,
                        const float* __restrict__ ssrc, const float* __restrict__ sdst,
                        const int* __restrict__ rowptr, const int* __restrict__ esrc,
                        const float* __restrict__ bias,
                        const float* __restrict__ gam, const float* __restrict__ bet,
                        const float* __restrict__ rm, const float* __restrict__ rv,
                        float* __restrict__ out)
{
    const int T = HEADS * 32;
    const int n = blockIdx.x;
    const int tid = threadIdx.x;
    const int head = tid >> 5;
    const int lane = tid & 31;
    const int start = rowptr[n];
    const int deg = rowptr[n + 1] - start;   // real in-edges; +1 implicit self loop

    float sd[HEADS];
#pragma unroll
    for (int h = 0; h < HEADS; h++) sd[h] = sdst[n * HEADS + h];

    // pass 1: per-head max over edges (incl. self loop at index deg)
    float ml[HEADS];
#pragma unroll
    for (int h = 0; h < HEADS; h++) ml[h] = -1e30f;
    for (int i = tid; i <= deg; i += T) {
        int s = (i == deg) ? n : esrc[start + i];
#pragma unroll
        for (int h = 0; h < HEADS; h++) {
            float e = ssrc[s * HEADS + h] + sd[h];
            e = e > 0.f ? e : 0.2f * e;
            ml[h] = fmaxf(ml[h], e);
        }
    }
#pragma unroll
    for (int h = 0; h < HEADS; h++)
#pragma unroll
        for (int off = 16; off; off >>= 1)
            ml[h] = fmaxf(ml[h], __shfl_xor_sync(0xffffffffu, ml[h], off));

    __shared__ float wmax[HEADS][HEADS];
    __shared__ float mmax[HEADS];
    float mAll[HEADS];
    if (HEADS > 1) {
        if (lane == 0) {
#pragma unroll
            for (int h = 0; h < HEADS; h++) wmax[head][h] = ml[h];
        }
        __syncthreads();
        if (tid < HEADS) {
            float m = wmax[0][tid];
#pragma unroll
            for (int w = 1; w < HEADS; w++) m = fmaxf(m, wmax[w][tid]);
            mmax[tid] = m;
        }
        __syncthreads();
#pragma unroll
        for (int h = 0; h < HEADS; h++) mAll[h] = mmax[h];
    } else {
        mAll[0] = ml[0];
    }

    // pass 2: chunked exp + weighted accumulate
    const int CHUNK = 128;
    __shared__ float sp[CHUNK][HEADS];
    __shared__ int sidx[CHUNK];
    float4 acc = make_float4(0.f, 0.f, 0.f, 0.f);
    float z = 0.f;

    for (int base = 0; base <= deg; base += CHUNK) {
        int len = min(CHUNK, deg + 1 - base);
        for (int i = tid; i < len; i += T) {
            int s = (base + i == deg) ? n : esrc[start + base + i];
            sidx[i] = s;
#pragma unroll
            for (int h = 0; h < HEADS; h++) {
                float e = ssrc[s * HEADS + h] + sd[h];
                e = e > 0.f ? e : 0.2f * e;
                sp[i][h] = __expf(e - mAll[h]);
            }
        }
        __syncthreads();
        for (int j = 0; j < len; j++) {
            float p = sp[j][head];
            z += p;
            int s = sidx[j];
            const float4 hv = *(const float4*)(hlin + (size_t)s * (HEADS * 128) + head * 128 + lane * 4);
            acc.x += p * hv.x;
            acc.y += p * hv.y;
            acc.z += p * hv.z;
            acc.w += p * hv.w;
        }
        __syncthreads();
    }

    float inv = 1.f / (z + 1e-16f);
    acc.x *= inv; acc.y *= inv; acc.z *= inv; acc.w *= inv;

    if (HEADS == 1) {
        float v[4] = {acc.x, acc.y, acc.z, acc.w};
#pragma unroll
        for (int k = 0; k < 4; k++) {
            int c = lane * 4 + k;
            out[(size_t)n * 128 + c] = v[k] + bias[c];
        }
    } else {
        __shared__ float hb[HEADS * 128];
        *(float4*)&hb[head * 128 + lane * 4] = acc;
        __syncthreads();
        if (tid < 32) {
#pragma unroll
            for (int k = 0; k < 4; k++) {
                int c = tid * 4 + k;
                float s = 0.f;
#pragma unroll
                for (int h = 0; h < HEADS; h++) s += hb[h * 128 + c];
                float v = s * (1.f / HEADS) + bias[c];
                if (ELUBN) {
                    v = v > 0.f ? v : (__expf(v) - 1.f);                       // ELU
                    v = (v - rm[c]) * rsqrtf(rv[c] + 1e-5f) * gam[c] + bet[c]; // BN eval
                    v = rtf32(v);   // pre-round for next layer's tensor-core GEMM
                }
                out[(size_t)n * 128 + c] = v;
            }
        }
    }
}

// ---------------- pooling ----------------
__global__ void pool_partial(const float* __restrict__ f, const int* __restrict__ batch,
                             float* __restrict__ tot, float* __restrict__ cnt)
{
    int n0 = blockIdx.x * 256;
    int c = threadIdx.x;
    if (n0 >= NN) return;
    int cur = batch[n0];
    float acc = 0.f;
    int lc = 0;
    for (int i = 0; i < 256; i++) {
        int n = n0 + i;
        if (n >= NN) break;
        int g = batch[n];
        if (g != cur) {
            atomicAdd(&tot[cur * 128 + c], acc);
            if (c == 0) atomicAdd(&cnt[cur], (float)lc);
            acc = 0.f; lc = 0; cur = g;
        }
        acc += f[(size_t)n * 128 + c];
        lc++;
    }
    if (lc) {
        atomicAdd(&tot[cur * 128 + c], acc);
        if (c == 0) atomicAdd(&cnt[cur], (float)lc);
    }
}

__global__ void pool_final(const float* __restrict__ tot, const float* __restrict__ cnt,
                           float* __restrict__ out)
{
    int g = blockIdx.x, c = threadIdx.x;
    out[g * 128 + c] = tot[g * 128 + c] / fmaxf(cnt[g], 1.f);
}

// ---------------- host orchestration ----------------
extern "C" void kernel_launch(void* const* d_in, const int* in_sizes, int n_in,
                              void* d_out, int out_size)
{
    const float* x    = (const float*)d_in[0];
    const int*   src  = (const int*)d_in[1];
    const int*   dst  = (const int*)d_in[2];
    const int*   batch= (const int*)d_in[3];
    const float* W1   = (const float*)d_in[4];
    const float* as1  = (const float*)d_in[5];
    const float* ad1  = (const float*)d_in[6];
    const float* b1   = (const float*)d_in[7];
    const float* gm1  = (const float*)d_in[8];
    const float* be1  = (const float*)d_in[9];
    const float* m1   = (const float*)d_in[10];
    const float* v1   = (const float*)d_in[11];
    const float* W2   = (const float*)d_in[12];
    const float* as2  = (const float*)d_in[13];
    const float* ad2  = (const float*)d_in[14];
    const float* b2   = (const float*)d_in[15];
    const float* gm2  = (const float*)d_in[16];
    const float* be2  = (const float*)d_in[17];
    const float* m2   = (const float*)d_in[18];
    const float* v2   = (const float*)d_in[19];
    const float* W3   = (const float*)d_in[20];
    const float* as3  = (const float*)d_in[21];
    const float* ad3  = (const float*)d_in[22];
    const float* b3   = (const float*)d_in[23];

    float *hlin, *xtf, *w1t, *w2t, *w3t, *f1, *f2, *f3, *ssrc, *sdst, *tot, *cnt;
    int *rowptr, *cursor, *deg, *esrc, *bsums;
    cudaGetSymbolAddress((void**)&hlin,  g_hlin);
    cudaGetSymbolAddress((void**)&xtf,   g_xtf);
    cudaGetSymbolAddress((void**)&w1t,   g_w1t);
    cudaGetSymbolAddress((void**)&w2t,   g_w2t);
    cudaGetSymbolAddress((void**)&w3t,   g_w3t);
    cudaGetSymbolAddress((void**)&f1,    g_f1);
    cudaGetSymbolAddress((void**)&f2,    g_f2);
    cudaGetSymbolAddress((void**)&f3,    g_f3);
    cudaGetSymbolAddress((void**)&ssrc,  g_ssrc);
    cudaGetSymbolAddress((void**)&sdst,  g_sdst);
    cudaGetSymbolAddress((void**)&rowptr,g_rowptr);
    cudaGetSymbolAddress((void**)&cursor,g_cursor);
    cudaGetSymbolAddress((void**)&deg,   g_deg);
    cudaGetSymbolAddress((void**)&esrc,  g_esrc);
    cudaGetSymbolAddress((void**)&bsums, g_bsums);
    cudaGetSymbolAddress((void**)&tot,   g_tot);
    cudaGetSymbolAddress((void**)&cnt,   g_cnt);

    static bool attr_set = false;
    if (!attr_set) {
        cudaFuncSetAttribute(gemm_tf32, cudaFuncAttributeMaxDynamicSharedMemorySize, GEMM_SMEM);
        attr_set = true;
    }

    const int MBLK = (NN + GBM - 1) / GBM;  // 157

    // --- pre-round GEMM operands (launches 0-3) ---
    round_tf32<<<(NN * DIN / 4 + 255) / 256, 256>>>(x, xtf, NN * DIN / 4);
    round_tf32<<<(DIN * 512 / 4 + 255) / 256, 256>>>(W1, w1t, DIN * 512 / 4);
    round_tf32<<<(128 * 512 / 4 + 255) / 256, 256>>>(W2, w2t, 128 * 512 / 4);
    round_tf32<<<(128 * 128 / 4 + 255) / 256, 256>>>(W3, w3t, 128 * 128 / 4);

    // launch 4
    kzero_i<<<(NN + 255) / 256, 256>>>(deg, NN);

    // --- layer 1 GEMM at launch index 5 (ncu -s 5 -c 1 profiles this) ---
    gemm_tf32<<<dim3(512 / GBN, MBLK), 256, GEMM_SMEM>>>(NN, 256, 512, xtf, w1t, hlin);

    // --- CSR build (counting sort by dst) ---
    hist_k<<<(EE + 255) / 256, 256>>>(dst, deg);
    scan_block<<<(NN + 1023) / 1024, 1024>>>(deg, rowptr, bsums, NN);
    scan_sums<<<1, 32>>>(bsums, (NN + 1023) / 1024);
    scan_add<<<(NN + 255) / 256, 256>>>(rowptr, cursor, bsums, NN);
    scatter_k<<<(EE + 255) / 256, 256>>>(src, dst, cursor, esrc);

    // --- layer 1 rest ---
    att_scores<4><<<NN, 128>>>(hlin, as1, ad1, ssrc, sdst);
    gat_agg<4, true><<<NN, 128>>>(hlin, ssrc, sdst, rowptr, esrc, b1, gm1, be1, m1, v1, f1);

    // --- layer 2: f1[40000,128] @ W2[128,512] ---
    gemm_tf32<<<dim3(512 / GBN, MBLK), 256, GEMM_SMEM>>>(NN, 128, 512, f1, w2t, hlin);
    att_scores<4><<<NN, 128>>>(hlin, as2, ad2, ssrc, sdst);
    gat_agg<4, true><<<NN, 128>>>(hlin, ssrc, sdst, rowptr, esrc, b2, gm2, be2, m2, v2, f2);

    // --- layer 3: f2[40000,128] @ W3[128,128], 1 head, no ELU/BN ---
    gemm_tf32<<<dim3(1, MBLK), 256, GEMM_SMEM>>>(NN, 128, 128, f2, w3t, hlin);
    att_scores<1><<<NN, 32>>>(hlin, as3, ad3, ssrc, sdst);
    gat_agg<1, false><<<NN, 32>>>(hlin, ssrc, sdst, rowptr, esrc, b3,
                                  nullptr, nullptr, nullptr, nullptr, f3);

    // --- global mean pool over sorted batch ---
    kzero_pool<<<(GG * 128 + 255) / 256, 256>>>(tot, cnt);
    pool_partial<<<(NN + 255) / 256, 128>>>(f3, batch, tot, cnt);
    pool_final<<<GG, 128>>>(tot, cnt, (float*)d_out);
}

// round 9
// speedup vs baseline: 1.0606x; 1.0606x over previous
#include <cuda_runtime.h>
#include <cuda_bf16.h>
#include <mma.h>
#include <cstdint>

using namespace nvcuda;

// Problem constants (fixed by the dataset)
#define NN 40000
#define EE 400000
#define GG 256
#define DIN 256
#define DHC 128      // channels per head
#define HH 4

#define MPAD 40064   // 313 * 128, padded rows for unguarded tensor-core stores

// ---------------- scratch (static device globals; no allocation) ----------------
__device__ float g_hlin[(size_t)MPAD * 512];   // linear output of current layer (padded)
__device__ float g_w2t[128 * 512];             // tf32-rounded weights (layers 2,3)
__device__ float g_w3t[128 * 128];
__device__ float g_f1[(size_t)NN * 128];       // layer1 out (tf32-rounded)
__device__ float g_f2[(size_t)NN * 128];       // layer2 out (tf32-rounded)
__device__ float g_f3[(size_t)NN * 128];       // layer3 out
__device__ float g_ssrc[NN * HH];
__device__ float g_sdst[NN * HH];
__device__ int   g_rowptr[NN + 1];
__device__ int   g_cursor[NN];
__device__ int   g_deg[NN];
__device__ int   g_esrc[EE];
__device__ int   g_bsums[64];
__device__ float g_tot[GG * 128];
__device__ float g_cnt[GG];

__device__ __forceinline__ float rtf32(float x) { return wmma::__float_to_tf32(x); }

// ---------------- utility kernels ----------------
__global__ void kzero_i(int* p, int n) {
    int i = blockIdx.x * blockDim.x + threadIdx.x;
    if (i < n) p[i] = 0;
}
// zero tot (GG*128) and cnt (GG) in one launch
__global__ void kzero_pool(float* tot, float* cnt) {
    int i = blockIdx.x * blockDim.x + threadIdx.x;
    if (i < GG * 128) tot[i] = 0.f;
    if (i < GG) cnt[i] = 0.f;
}

// round float array to tf32 (float4-vectorized; n % 4 == 0)
__global__ void round_tf32(const float* __restrict__ in, float* __restrict__ out, int n4) {
    int i = blockIdx.x * blockDim.x + threadIdx.x;
    if (i < n4) {
        float4 v = ((const float4*)in)[i];
        v.x = rtf32(v.x); v.y = rtf32(v.y); v.z = rtf32(v.z); v.w = rtf32(v.w);
        ((float4*)out)[i] = v;
    }
}

__global__ void hist_k(const int* __restrict__ dst, int* __restrict__ deg) {
    int e = blockIdx.x * blockDim.x + threadIdx.x;
    if (e < EE) atomicAdd(&deg[dst[e]], 1);
}

// block-wise exclusive scan (1024 per block) + block totals
__global__ void scan_block(const int* __restrict__ deg, int* __restrict__ rowptr,
                           int* __restrict__ bsums, int n) {
    __shared__ int tmp[1024];
    int i = blockIdx.x * 1024 + threadIdx.x;
    int v = (i < n) ? deg[i] : 0;
    tmp[threadIdx.x] = v;
    __syncthreads();
    for (int off = 1; off < 1024; off <<= 1) {
        int t = (threadIdx.x >= off) ? tmp[threadIdx.x - off] : 0;
        __syncthreads();
        tmp[threadIdx.x] += t;
        __syncthreads();
    }
    if (i < n) rowptr[i] = tmp[threadIdx.x] - v;  // exclusive
    if (threadIdx.x == 1023) bsums[blockIdx.x] = tmp[1023];
}

__global__ void scan_sums(int* bsums, int nb) {
    if (threadIdx.x == 0 && blockIdx.x == 0) {
        int run = 0;
        for (int b = 0; b < nb; b++) { int v = bsums[b]; bsums[b] = run; run += v; }
    }
}

__global__ void scan_add(int* __restrict__ rowptr, int* __restrict__ cursor,
                         const int* __restrict__ bsums, int n) {
    int i = blockIdx.x * blockDim.x + threadIdx.x;
    if (i < n) {
        int v = rowptr[i] + bsums[i >> 10];
        rowptr[i] = v;
        cursor[i] = v;
    }
    if (i == 0) rowptr[n] = EE;
}

__global__ void scatter_k(const int* __restrict__ src, const int* __restrict__ dst,
                          int* __restrict__ cursor, int* __restrict__ esrc) {
    int e = blockIdx.x * blockDim.x + threadIdx.x;
    if (e < EE) {
        int pos = atomicAdd(&cursor[dst[e]], 1);
        esrc[pos] = src[e];
    }
}

// ---------------- TF32 tensor-core GEMM, cp.async double-buffered ----------------
// C[M,Nc] = A[M,K] @ B[K,Nc]. If CVT, operands are rounded to tf32 in-register
// per fragment; otherwise they must be pre-rounded in memory.
// Block tile 128x128, BK=16, 8 warps (4M x 2N), warp tile 32x64 = 2x4 wmma
// 16x16x8 tf32. K % 16 == 0, Nc % 128 == 0. C rows padded (MPAD) so stores are
// unguarded; A rows guarded by cp.async zero-size fill.
#define GBM 128
#define GBN 128
#define GBK 16
#define GLDA 20    // 16 + 4 pad (floats); 80B row stride, 16B aligned
#define GLDB 132   // 128 + 4 pad (floats); 528B row stride, 16B aligned

template <bool CVT>
__global__ __launch_bounds__(256) void gemm_tf32(int M, int K, int Nc,
    const float* __restrict__ A, const float* __restrict__ B, float* __restrict__ C)
{
    __shared__ __align__(16) float As[2][GBM * GLDA];
    __shared__ __align__(16) float Bs[2][GBK * GLDB];

    const int tid = threadIdx.x;
    const int warpId = tid >> 5;
    const int warpM = warpId & 3;      // M offset warpM*32
    const int warpN = warpId >> 2;     // N offset warpN*64
    const int blockM = blockIdx.y * GBM;
    const int blockN = blockIdx.x * GBN;

    const unsigned int sA = (unsigned int)__cvta_generic_to_shared(&As[0][0]);
    const unsigned int sB = (unsigned int)__cvta_generic_to_shared(&Bs[0][0]);

    wmma::fragment<wmma::accumulator, 16, 16, 8, float> acc[2][4];
#pragma unroll
    for (int i = 0; i < 2; i++)
#pragma unroll
        for (int j = 0; j < 4; j++) wmma::fill_fragment(acc[i][j], 0.f);

    const int nsteps = K / GBK;

    // --- staging: 512 float4 chunks each for A and B, 2 per thread ---
    auto stage = [&](int buf, int k0) {
#pragma unroll
        for (int q = 0; q < 2; q++) {
            int c = tid + q * 256;
            // A: chunk c -> row c>>2, col-group c&3
            int ar = c >> 2, ac = (c & 3) * 4;
            int gr = blockM + ar;
            const float* gpA = A + (size_t)gr * K + k0 + ac;
            unsigned int saA = sA + (unsigned int)(buf * GBM * GLDA + ar * GLDA + ac) * 4u;
            int sz = (gr < M) ? 16 : 0;
            asm volatile("cp.async.cg.shared.global [%0], [%1], 16, %2;\n"
                         :: "r"(saA), "l"(gpA), "r"(sz));
            // B: chunk c -> row c>>5, col (c&31)*4
            int br = c >> 5, bc = (c & 31) * 4;
            const float* gpB = B + (size_t)(k0 + br) * Nc + blockN + bc;
            unsigned int saB = sB + (unsigned int)(buf * GBK * GLDB + br * GLDB + bc) * 4u;
            asm volatile("cp.async.cg.shared.global [%0], [%1], 16;\n"
                         :: "r"(saB), "l"(gpB));
        }
        asm volatile("cp.async.commit_group;\n");
    };

    stage(0, 0);

    for (int s = 0; s < nsteps; s++) {
        const int p = s & 1;
        if (s + 1 < nsteps) {
            stage(1 - p, (s + 1) * GBK);
            asm volatile("cp.async.wait_group 1;\n");
        } else {
            asm volatile("cp.async.wait_group 0;\n");
        }
        __syncthreads();

        const float* ap = &As[p][0];
        const float* bp = &Bs[p][0];
#pragma unroll
        for (int kk = 0; kk < GBK; kk += 8) {
            wmma::fragment<wmma::matrix_a, 16, 16, 8, wmma::precision::tf32, wmma::row_major> af[2];
            wmma::fragment<wmma::matrix_b, 16, 16, 8, wmma::precision::tf32, wmma::row_major> bf[4];
#pragma unroll
            for (int i = 0; i < 2; i++) {
                wmma::load_matrix_sync(af[i], ap + (warpM * 32 + i * 16) * GLDA + kk, GLDA);
                if (CVT) {
#pragma unroll
                    for (int t = 0; t < af[i].num_elements; t++)
                        af[i].x[t] = rtf32(af[i].x[t]);
                }
            }
#pragma unroll
            for (int j = 0; j < 4; j++) {
                wmma::load_matrix_sync(bf[j], bp + kk * GLDB + warpN * 64 + j * 16, GLDB);
                if (CVT) {
#pragma unroll
                    for (int t = 0; t < bf[j].num_elements; t++)
                        bf[j].x[t] = rtf32(bf[j].x[t]);
                }
            }
#pragma unroll
            for (int i = 0; i < 2; i++)
#pragma unroll
                for (int j = 0; j < 4; j++)
                    wmma::mma_sync(acc[i][j], af[i], bf[j], acc[i][j]);
        }
        __syncthreads();
    }

#pragma unroll
    for (int i = 0; i < 2; i++)
#pragma unroll
        for (int j = 0; j < 4; j++) {
            size_t row = blockM + warpM * 32 + i * 16;
            wmma::store_matrix_sync(C + row * Nc + blockN + warpN * 64 + j * 16,
                                    acc[i][j], Nc, wmma::mem_row_major);
        }
}

// ---------------- attention scores: s_src[n,h], s_dst[n,h] ----------------
template <int HEADS>
__global__ void att_scores(const float* __restrict__ h, const float* __restrict__ asrc,
                           const float* __restrict__ adst, float* __restrict__ ssrc,
                           float* __restrict__ sdst)
{
    const int n = blockIdx.x;
    const int w = threadIdx.x >> 5;
    const int lane = threadIdx.x & 31;
    const float4 hv = *(const float4*)(h + (size_t)n * HEADS * 128 + w * 128 + lane * 4);
    const float4 av = *(const float4*)(asrc + w * 128 + lane * 4);
    const float4 dv = *(const float4*)(adst + w * 128 + lane * 4);
    float a = hv.x * av.x + hv.y * av.y + hv.z * av.z + hv.w * av.w;
    float d = hv.x * dv.x + hv.y * dv.y + hv.z * dv.z + hv.w * dv.w;
#pragma unroll
    for (int off = 16; off; off >>= 1) {
        a += __shfl_xor_sync(0xffffffffu, a, off);
        d += __shfl_xor_sync(0xffffffffu, d, off);
    }
    if (lane == 0) {
        ssrc[n * HEADS + w] = a;
        sdst[n * HEADS + w] = d;
    }
}

// ---------------- per-dst aggregation + epilogue ----------------
// ELUBN layers also round their outputs to tf32 (they feed the next GEMM).
template <int HEADS, bool ELUBN>
__global__ void gat_agg(const float* __restrict__ hlin,
                        const float* __restrict__ ssrc, const float* __restrict__ sdst,
                        const int* __restrict__ rowptr, const int* __restrict__ esrc,
                        const float* __restrict__ bias,
                        const float* __restrict__ gam, const float* __restrict__ bet,
                        const float* __restrict__ rm, const float* __restrict__ rv,
                        float* __restrict__ out)
{
    const int T = HEADS * 32;
    const int n = blockIdx.x;
    const int tid = threadIdx.x;
    const int head = tid >> 5;
    const int lane = tid & 31;
    const int start = rowptr[n];
    const int deg = rowptr[n + 1] - start;   // real in-edges; +1 implicit self loop

    float sd[HEADS];
#pragma unroll
    for (int h = 0; h < HEADS; h++) sd[h] = sdst[n * HEADS + h];

    // pass 1: per-head max over edges (incl. self loop at index deg)
    float ml[HEADS];
#pragma unroll
    for (int h = 0; h < HEADS; h++) ml[h] = -1e30f;
    for (int i = tid; i <= deg; i += T) {
        int s = (i == deg) ? n : esrc[start + i];
#pragma unroll
        for (int h = 0; h < HEADS; h++) {
            float e = ssrc[s * HEADS + h] + sd[h];
            e = e > 0.f ? e : 0.2f * e;
            ml[h] = fmaxf(ml[h], e);
        }
    }
#pragma unroll
    for (int h = 0; h < HEADS; h++)
#pragma unroll
        for (int off = 16; off; off >>= 1)
            ml[h] = fmaxf(ml[h], __shfl_xor_sync(0xffffffffu, ml[h], off));

    __shared__ float wmax[HEADS][HEADS];
    __shared__ float mmax[HEADS];
    float mAll[HEADS];
    if (HEADS > 1) {
        if (lane == 0) {
#pragma unroll
            for (int h = 0; h < HEADS; h++) wmax[head][h] = ml[h];
        }
        __syncthreads();
        if (tid < HEADS) {
            float m = wmax[0][tid];
#pragma unroll
            for (int w = 1; w < HEADS; w++) m = fmaxf(m, wmax[w][tid]);
            mmax[tid] = m;
        }
        __syncthreads();
#pragma unroll
        for (int h = 0; h < HEADS; h++) mAll[h] = mmax[h];
    } else {
        mAll[0] = ml[0];
    }

    // pass 2: chunked exp + weighted accumulate
    const int CHUNK = 128;
    __shared__ float sp[CHUNK][HEADS];
    __shared__ int sidx[CHUNK];
    float4 acc = make_float4(0.f, 0.f, 0.f, 0.f);
    float z = 0.f;

    for (int base = 0; base <= deg; base += CHUNK) {
        int len = min(CHUNK, deg + 1 - base);
        for (int i = tid; i < len; i += T) {
            int s = (base + i == deg) ? n : esrc[start + base + i];
            sidx[i] = s;
#pragma unroll
            for (int h = 0; h < HEADS; h++) {
                float e = ssrc[s * HEADS + h] + sd[h];
                e = e > 0.f ? e : 0.2f * e;
                sp[i][h] = __expf(e - mAll[h]);
            }
        }
        __syncthreads();
        for (int j = 0; j < len; j++) {
            float p = sp[j][head];
            z += p;
            int s = sidx[j];
            const float4 hv = *(const float4*)(hlin + (size_t)s * (HEADS * 128) + head * 128 + lane * 4);
            acc.x += p * hv.x;
            acc.y += p * hv.y;
            acc.z += p * hv.z;
            acc.w += p * hv.w;
        }
        __syncthreads();
    }

    float inv = 1.f / (z + 1e-16f);
    acc.x *= inv; acc.y *= inv; acc.z *= inv; acc.w *= inv;

    if (HEADS == 1) {
        float v[4] = {acc.x, acc.y, acc.z, acc.w};
#pragma unroll
        for (int k = 0; k < 4; k++) {
            int c = lane * 4 + k;
            out[(size_t)n * 128 + c] = v[k] + bias[c];
        }
    } else {
        __shared__ float hb[HEADS * 128];
        *(float4*)&hb[head * 128 + lane * 4] = acc;
        __syncthreads();
        if (tid < 32) {
#pragma unroll
            for (int k = 0; k < 4; k++) {
                int c = tid * 4 + k;
                float s = 0.f;
#pragma unroll
                for (int h = 0; h < HEADS; h++) s += hb[h * 128 + c];
                float v = s * (1.f / HEADS) + bias[c];
                if (ELUBN) {
                    v = v > 0.f ? v : (__expf(v) - 1.f);                       // ELU
                    v = (v - rm[c]) * rsqrtf(rv[c] + 1e-5f) * gam[c] + bet[c]; // BN eval
                    v = rtf32(v);   // pre-round for next layer's tensor-core GEMM
                }
                out[(size_t)n * 128 + c] = v;
            }
        }
    }
}

// ---------------- pooling ----------------
__global__ void pool_partial(const float* __restrict__ f, const int* __restrict__ batch,
                             float* __restrict__ tot, float* __restrict__ cnt)
{
    int n0 = blockIdx.x * 256;
    int c = threadIdx.x;
    if (n0 >= NN) return;
    int cur = batch[n0];
    float acc = 0.f;
    int lc = 0;
    for (int i = 0; i < 256; i++) {
        int n = n0 + i;
        if (n >= NN) break;
        int g = batch[n];
        if (g != cur) {
            atomicAdd(&tot[cur * 128 + c], acc);
            if (c == 0) atomicAdd(&cnt[cur], (float)lc);
            acc = 0.f; lc = 0; cur = g;
        }
        acc += f[(size_t)n * 128 + c];
        lc++;
    }
    if (lc) {
        atomicAdd(&tot[cur * 128 + c], acc);
        if (c == 0) atomicAdd(&cnt[cur], (float)lc);
    }
}

__global__ void pool_final(const float* __restrict__ tot, const float* __restrict__ cnt,
                           float* __restrict__ out)
{
    int g = blockIdx.x, c = threadIdx.x;
    out[g * 128 + c] = tot[g * 128 + c] / fmaxf(cnt[g], 1.f);
}

// ---------------- host orchestration ----------------
extern "C" void kernel_launch(void* const* d_in, const int* in_sizes, int n_in,
                              void* d_out, int out_size)
{
    const float* x    = (const float*)d_in[0];
    const int*   src  = (const int*)d_in[1];
    const int*   dst  = (const int*)d_in[2];
    const int*   batch= (const int*)d_in[3];
    const float* W1   = (const float*)d_in[4];
    const float* as1  = (const float*)d_in[5];
    const float* ad1  = (const float*)d_in[6];
    const float* b1   = (const float*)d_in[7];
    const float* gm1  = (const float*)d_in[8];
    const float* be1  = (const float*)d_in[9];
    const float* m1   = (const float*)d_in[10];
    const float* v1   = (const float*)d_in[11];
    const float* W2   = (const float*)d_in[12];
    const float* as2  = (const float*)d_in[13];
    const float* ad2  = (const float*)d_in[14];
    const float* b2   = (const float*)d_in[15];
    const float* gm2  = (const float*)d_in[16];
    const float* be2  = (const float*)d_in[17];
    const float* m2   = (const float*)d_in[18];
    const float* v2   = (const float*)d_in[19];
    const float* W3   = (const float*)d_in[20];
    const float* as3  = (const float*)d_in[21];
    const float* ad3  = (const float*)d_in[22];
    const float* b3   = (const float*)d_in[23];

    float *hlin, *w2t, *w3t, *f1, *f2, *f3, *ssrc, *sdst, *tot, *cnt;
    int *rowptr, *cursor, *deg, *esrc, *bsums;
    cudaGetSymbolAddress((void**)&hlin,  g_hlin);
    cudaGetSymbolAddress((void**)&w2t,   g_w2t);
    cudaGetSymbolAddress((void**)&w3t,   g_w3t);
    cudaGetSymbolAddress((void**)&f1,    g_f1);
    cudaGetSymbolAddress((void**)&f2,    g_f2);
    cudaGetSymbolAddress((void**)&f3,    g_f3);
    cudaGetSymbolAddress((void**)&ssrc,  g_ssrc);
    cudaGetSymbolAddress((void**)&sdst,  g_sdst);
    cudaGetSymbolAddress((void**)&rowptr,g_rowptr);
    cudaGetSymbolAddress((void**)&cursor,g_cursor);
    cudaGetSymbolAddress((void**)&deg,   g_deg);
    cudaGetSymbolAddress((void**)&esrc,  g_esrc);
    cudaGetSymbolAddress((void**)&bsums, g_bsums);
    cudaGetSymbolAddress((void**)&tot,   g_tot);
    cudaGetSymbolAddress((void**)&cnt,   g_cnt);

    // side streams + events (created once; creation is host-side, not dev alloc)
    static cudaStream_t sB = nullptr, sC = nullptr;
    static cudaEvent_t evFork = nullptr, evB = nullptr, evC = nullptr;
    if (!sB) {
        cudaStreamCreateWithFlags(&sB, cudaStreamNonBlocking);
        cudaStreamCreateWithFlags(&sC, cudaStreamNonBlocking);
        cudaEventCreateWithFlags(&evFork, cudaEventDisableTiming);
        cudaEventCreateWithFlags(&evB, cudaEventDisableTiming);
        cudaEventCreateWithFlags(&evC, cudaEventDisableTiming);
    }

    const int MB = (NN + 127) / 128;  // 313

    // ---- fork ----
    cudaEventRecord(evFork, 0);
    cudaStreamWaitEvent(sB, evFork, 0);
    cudaStreamWaitEvent(sC, evFork, 0);

    // ---- stream B: CSR build (counting sort by dst) ----
    kzero_i<<<(NN + 255) / 256, 256, 0, sB>>>(deg, NN);
    hist_k<<<(EE + 255) / 256, 256, 0, sB>>>(dst, deg);
    scan_block<<<(NN + 1023) / 1024, 1024, 0, sB>>>(deg, rowptr, bsums, NN);
    scan_sums<<<1, 32, 0, sB>>>(bsums, (NN + 1023) / 1024);
    scan_add<<<(NN + 255) / 256, 256, 0, sB>>>(rowptr, cursor, bsums, NN);
    scatter_k<<<(EE + 255) / 256, 256, 0, sB>>>(src, dst, cursor, esrc);
    cudaEventRecord(evB, sB);

    // ---- stream C: weight rounding (layers 2,3) + pool zeroing ----
    round_tf32<<<(128 * 512 / 4 + 255) / 256, 256, 0, sC>>>(W2, w2t, 128 * 512 / 4);
    round_tf32<<<(128 * 128 / 4 + 255) / 256, 256, 0, sC>>>(W3, w3t, 128 * 128 / 4);
    kzero_pool<<<(GG * 128 + 255) / 256, 256, 0, sC>>>(tot, cnt);
    cudaEventRecord(evC, sC);

    // ---- main stream: layer 1 (in-fragment cvt; raw x, W1) ----
    gemm_tf32<true><<<dim3(4, MB), 256>>>(NN, 256, 512, x, W1, hlin);
    att_scores<4><<<NN, 128>>>(hlin, as1, ad1, ssrc, sdst);
    cudaStreamWaitEvent(0, evB, 0);   // need CSR for aggregation
    gat_agg<4, true><<<NN, 128>>>(hlin, ssrc, sdst, rowptr, esrc, b1, gm1, be1, m1, v1, f1);

    // ---- layer 2: f1 (pre-rounded) @ w2t ----
    cudaStreamWaitEvent(0, evC, 0);   // need rounded W2/W3 + zeroed pool bufs
    gemm_tf32<false><<<dim3(4, MB), 256>>>(NN, 128, 512, f1, w2t, hlin);
    att_scores<4><<<NN, 128>>>(hlin, as2, ad2, ssrc, sdst);
    gat_agg<4, true><<<NN, 128>>>(hlin, ssrc, sdst, rowptr, esrc, b2, gm2, be2, m2, v2, f2);

    // ---- layer 3: f2 (pre-rounded) @ w3t, 1 head, no ELU/BN ----
    gemm_tf32<false><<<dim3(1, MB), 256>>>(NN, 128, 128, f2, w3t, hlin);
    att_scores<1><<<NN, 32>>>(hlin, as3, ad3, ssrc, sdst);
    gat_agg<1, false><<<NN, 32>>>(hlin, ssrc, sdst, rowptr, esrc, b3,
                                  nullptr, nullptr, nullptr, nullptr, f3);

    // ---- global mean pool over sorted batch ----
    pool_partial<<<(NN + 255) / 256, 128>>>(f3, batch, tot, cnt);
    pool_final<<<GG, 128>>>(tot, cnt, (float*)d_out);
}

// round 10
// speedup vs baseline: 1.9101x; 1.8010x over previous
#include <cuda_runtime.h>
#include <cuda_fp16.h>
#include <mma.h>
#include <cstdint>

using namespace nvcuda;

// Problem constants (fixed by the dataset)
#define NN 40000
#define EE 400000
#define GG 256
#define DIN 256
#define HH 4

#define MPAD 40064   // 313 * 128, padded rows for unguarded stores

// ---------------- scratch (static device globals; no allocation) ----------------
__device__ __half g_hlinh[(size_t)MPAD * 512];  // GEMM output (half), current layer
__device__ __half g_xh[(size_t)NN * DIN];       // x converted to half
__device__ __half g_w1h[DIN * 512];
__device__ __half g_w2h[128 * 512];
__device__ __half g_w3h[128 * 128];
__device__ __half g_f1h[(size_t)NN * 128];      // layer1 out (half)
__device__ __half g_f2h[(size_t)NN * 128];      // layer2 out (half)
__device__ float  g_f3[(size_t)NN * 128];       // layer3 out (float, feeds pool)
__device__ float  g_ssrc[NN * HH];
__device__ float  g_sdst[NN * HH];
__device__ int    g_rowptr[NN + 1];
__device__ int    g_cursor[NN];
__device__ int    g_deg[NN];
__device__ int    g_esrc[EE];
__device__ int    g_bsums[64];
__device__ float  g_tot[GG * 128];
__device__ float  g_cnt[GG];

// ---------------- utility kernels ----------------
__global__ void kzero_i(int* p, int n) {
    int i = blockIdx.x * blockDim.x + threadIdx.x;
    if (i < n) p[i] = 0;
}
__global__ void kzero_pool(float* tot, float* cnt) {
    int i = blockIdx.x * blockDim.x + threadIdx.x;
    if (i < GG * 128) tot[i] = 0.f;
    if (i < GG) cnt[i] = 0.f;
}

// convert fp32 array to half, 8 elements per thread (n % 8 == 0)
__global__ void conv_half(const float* __restrict__ in, __half* __restrict__ out, int n8) {
    int i = blockIdx.x * blockDim.x + threadIdx.x;
    if (i < n8) {
        float4 a = ((const float4*)in)[2 * i];
        float4 b = ((const float4*)in)[2 * i + 1];
        __half2 h[4];
        h[0] = __floats2half2_rn(a.x, a.y);
        h[1] = __floats2half2_rn(a.z, a.w);
        h[2] = __floats2half2_rn(b.x, b.y);
        h[3] = __floats2half2_rn(b.z, b.w);
        ((uint4*)out)[i] = *(uint4*)h;
    }
}

__global__ void hist_k(const int* __restrict__ dst, int* __restrict__ deg) {
    int e = blockIdx.x * blockDim.x + threadIdx.x;
    if (e < EE) atomicAdd(&deg[dst[e]], 1);
}

__global__ void scan_block(const int* __restrict__ deg, int* __restrict__ rowptr,
                           int* __restrict__ bsums, int n) {
    __shared__ int tmp[1024];
    int i = blockIdx.x * 1024 + threadIdx.x;
    int v = (i < n) ? deg[i] : 0;
    tmp[threadIdx.x] = v;
    __syncthreads();
    for (int off = 1; off < 1024; off <<= 1) {
        int t = (threadIdx.x >= off) ? tmp[threadIdx.x - off] : 0;
        __syncthreads();
        tmp[threadIdx.x] += t;
        __syncthreads();
    }
    if (i < n) rowptr[i] = tmp[threadIdx.x] - v;  // exclusive
    if (threadIdx.x == 1023) bsums[blockIdx.x] = tmp[1023];
}

__global__ void scan_sums(int* bsums, int nb) {
    if (threadIdx.x == 0 && blockIdx.x == 0) {
        int run = 0;
        for (int b = 0; b < nb; b++) { int v = bsums[b]; bsums[b] = run; run += v; }
    }
}

__global__ void scan_add(int* __restrict__ rowptr, int* __restrict__ cursor,
                         const int* __restrict__ bsums, int n) {
    int i = blockIdx.x * blockDim.x + threadIdx.x;
    if (i < n) {
        int v = rowptr[i] + bsums[i >> 10];
        rowptr[i] = v;
        cursor[i] = v;
    }
    if (i == 0) rowptr[n] = EE;
}

__global__ void scatter_k(const int* __restrict__ src, const int* __restrict__ dst,
                          int* __restrict__ cursor, int* __restrict__ esrc) {
    int e = blockIdx.x * blockDim.x + threadIdx.x;
    if (e < EE) {
        int pos = atomicAdd(&cursor[dst[e]], 1);
        esrc[pos] = src[e];
    }
}

// ---------------- FP16 tensor-core GEMM + fused attention-score epilogue ----------
// C[M,Nc] = A[M,K] @ B[K,Nc], A/B half, C half. Block tile 128x128, BK=32,
// 8 warps (4M x 2N), warp 32x64 = 2x4 wmma 16x16x16, fp32 accum.
// grid.x == heads (Nc = heads*128): each block owns one head's full 128 channels,
// so it also computes ssrc/sdst dots for its 128 rows (no atomics).
// K % 32 == 0. C rows padded (MPAD); A rows guarded by cp.async zero-fill.
#define GBM 128
#define GBN 128
#define GBK 32
#define ALD 40     // A smem row stride (halfs): 32 + 8 pad; 80B, 16B-mult
#define BLD 136    // B smem row stride (halfs): 128 + 8 pad; 272B, 16B-mult
#define AB_BYTES (2 * GBM * ALD * 2 + 2 * GBK * BLD * 2)   // 37888
#define CS_LD 68   // epilogue float staging stride (68 % 4 == 0)

__global__ __launch_bounds__(256) void gemm_h(int M, int K, int Nc,
    const __half* __restrict__ A, const __half* __restrict__ B, __half* __restrict__ C,
    int heads, const float* __restrict__ asrc, const float* __restrict__ adst,
    float* __restrict__ ssrc, float* __restrict__ sdst)
{
    __shared__ __align__(16) char smem_raw[AB_BYTES];   // 37.9KB, reused by epilogue
    __half* Ah = (__half*)smem_raw;                     // [2][GBM*ALD]
    __half* Bh = Ah + 2 * GBM * ALD;                    // [2][GBK*BLD]

    const int tid = threadIdx.x;
    const int warpId = tid >> 5;
    const int warpM = warpId & 3;      // M offset warpM*32
    const int warpN = warpId >> 2;     // N offset warpN*64
    const int head = blockIdx.x;
    const int blockM = blockIdx.y * GBM;
    const int blockN = head * GBN;

    const unsigned int sA = (unsigned int)__cvta_generic_to_shared(Ah);
    const unsigned int sB = (unsigned int)__cvta_generic_to_shared(Bh);

    wmma::fragment<wmma::accumulator, 16, 16, 16, float> acc[2][4];
#pragma unroll
    for (int i = 0; i < 2; i++)
#pragma unroll
        for (int j = 0; j < 4; j++) wmma::fill_fragment(acc[i][j], 0.f);

    const int nsteps = K / GBK;

    // staging: A = 512 16B chunks (row c>>2, 8-half group c&3); B = 512 (row c>>4, group c&15)
    auto stage = [&](int buf, int k0) {
#pragma unroll
        for (int q = 0; q < 2; q++) {
            int c = tid + q * 256;
            int ar = c >> 2, ac = (c & 3) * 8;
            int gr = blockM + ar;
            const __half* gpA = A + (size_t)gr * K + k0 + ac;
            unsigned int saA = sA + (unsigned int)(buf * GBM * ALD + ar * ALD + ac) * 2u;
            int sz = (gr < M) ? 16 : 0;
            asm volatile("cp.async.cg.shared.global [%0], [%1], 16, %2;\n"
                         :: "r"(saA), "l"(gpA), "r"(sz));
            int br = c >> 4, bc = (c & 15) * 8;
            const __half* gpB = B + (size_t)(k0 + br) * Nc + blockN + bc;
            unsigned int saB = sB + (unsigned int)(buf * GBK * BLD + br * BLD + bc) * 2u;
            asm volatile("cp.async.cg.shared.global [%0], [%1], 16;\n"
                         :: "r"(saB), "l"(gpB));
        }
        asm volatile("cp.async.commit_group;\n");
    };

    stage(0, 0);

    for (int s = 0; s < nsteps; s++) {
        const int p = s & 1;
        if (s + 1 < nsteps) {
            stage(1 - p, (s + 1) * GBK);
            asm volatile("cp.async.wait_group 1;\n");
        } else {
            asm volatile("cp.async.wait_group 0;\n");
        }
        __syncthreads();

        const __half* ap = Ah + p * GBM * ALD;
        const __half* bp = Bh + p * GBK * BLD;
#pragma unroll
        for (int kk = 0; kk < GBK; kk += 16) {
            wmma::fragment<wmma::matrix_a, 16, 16, 16, __half, wmma::row_major> af[2];
            wmma::fragment<wmma::matrix_b, 16, 16, 16, __half, wmma::row_major> bf[4];
#pragma unroll
            for (int i = 0; i < 2; i++)
                wmma::load_matrix_sync(af[i], ap + (warpM * 32 + i * 16) * ALD + kk, ALD);
#pragma unroll
            for (int j = 0; j < 4; j++)
                wmma::load_matrix_sync(bf[j], bp + kk * BLD + warpN * 64 + j * 16, BLD);
#pragma unroll
            for (int i = 0; i < 2; i++)
#pragma unroll
                for (int j = 0; j < 4; j++)
                    wmma::mma_sync(acc[i][j], af[i], bf[j], acc[i][j]);
        }
        __syncthreads();
    }

    // ---- fused epilogue: acc -> smem(fp32) -> half C + attention dots ----
    float* Cs = (float*)smem_raw;            // [128][CS_LD]
    const float* asrc_h = asrc + head * 128;
    const float* adst_h = adst + head * 128;
    const int row = tid >> 1;
    const int cseg = (tid & 1) * 32;
    float ds = 0.f, dd = 0.f;

#pragma unroll
    for (int p = 0; p < 2; p++) {            // warpN halves: cols [p*64, p*64+64)
        if (warpN == p) {
#pragma unroll
            for (int i = 0; i < 2; i++)
#pragma unroll
                for (int j = 0; j < 4; j++)
                    wmma::store_matrix_sync(Cs + (warpM * 32 + i * 16) * CS_LD + j * 16,
                                            acc[i][j], CS_LD, wmma::mem_row_major);
        }
        __syncthreads();

        const float* crow = Cs + row * CS_LD + cseg;
        __half2 hbuf[16];
        int colbase = p * 64 + cseg;
#pragma unroll
        for (int k = 0; k < 32; k += 2) {
            float a0 = crow[k], a1 = crow[k + 1];
            hbuf[k >> 1] = __floats2half2_rn(a0, a1);
            ds += a0 * asrc_h[colbase + k] + a1 * asrc_h[colbase + k + 1];
            dd += a0 * adst_h[colbase + k] + a1 * adst_h[colbase + k + 1];
        }
        uint4* dstp = (uint4*)(C + (size_t)(blockM + row) * Nc + blockN + colbase);
        const uint4* srcv = (const uint4*)hbuf;
        dstp[0] = srcv[0]; dstp[1] = srcv[1]; dstp[2] = srcv[2]; dstp[3] = srcv[3];
        __syncthreads();
    }

    ds += __shfl_xor_sync(0xffffffffu, ds, 1);
    dd += __shfl_xor_sync(0xffffffffu, dd, 1);
    int gr = blockM + row;
    if ((tid & 1) == 0 && gr < M) {
        ssrc[gr * heads + head] = ds;
        sdst[gr * heads + head] = dd;
    }
}

// ---------------- per-dst aggregation + epilogue (half hlin) ----------------
template <int HEADS, bool ELUBN>
__global__ void gat_agg(const __half* __restrict__ hlin,
                        const float* __restrict__ ssrc, const float* __restrict__ sdst,
                        const int* __restrict__ rowptr, const int* __restrict__ esrc,
                        const float* __restrict__ bias,
                        const float* __restrict__ gam, const float* __restrict__ bet,
                        const float* __restrict__ rm, const float* __restrict__ rv,
                        __half* __restrict__ outh, float* __restrict__ outf)
{
    const int T = HEADS * 32;
    const int n = blockIdx.x;
    const int tid = threadIdx.x;
    const int head = tid >> 5;
    const int lane = tid & 31;
    const int start = rowptr[n];
    const int deg = rowptr[n + 1] - start;   // real in-edges; +1 implicit self loop

    float sd[HEADS];
#pragma unroll
    for (int h = 0; h < HEADS; h++) sd[h] = sdst[n * HEADS + h];

    // pass 1: per-head max over edges (incl. self loop at index deg)
    float ml[HEADS];
#pragma unroll
    for (int h = 0; h < HEADS; h++) ml[h] = -1e30f;
    for (int i = tid; i <= deg; i += T) {
        int s = (i == deg) ? n : esrc[start + i];
#pragma unroll
        for (int h = 0; h < HEADS; h++) {
            float e = ssrc[s * HEADS + h] + sd[h];
            e = e > 0.f ? e : 0.2f * e;
            ml[h] = fmaxf(ml[h], e);
        }
    }
#pragma unroll
    for (int h = 0; h < HEADS; h++)
#pragma unroll
        for (int off = 16; off; off >>= 1)
            ml[h] = fmaxf(ml[h], __shfl_xor_sync(0xffffffffu, ml[h], off));

    __shared__ float wmax[HEADS][HEADS];
    __shared__ float mmax[HEADS];
    float mAll[HEADS];
    if (HEADS > 1) {
        if (lane == 0) {
#pragma unroll
            for (int h = 0; h < HEADS; h++) wmax[head][h] = ml[h];
        }
        __syncthreads();
        if (tid < HEADS) {
            float m = wmax[0][tid];
#pragma unroll
            for (int w = 1; w < HEADS; w++) m = fmaxf(m, wmax[w][tid]);
            mmax[tid] = m;
        }
        __syncthreads();
#pragma unroll
        for (int h = 0; h < HEADS; h++) mAll[h] = mmax[h];
    } else {
        mAll[0] = ml[0];
    }

    // pass 2: chunked exp + weighted accumulate (half gathers)
    const int CHUNK = 128;
    __shared__ float sp[CHUNK][HEADS];
    __shared__ int sidx[CHUNK];
    float4 acc = make_float4(0.f, 0.f, 0.f, 0.f);
    float z = 0.f;

    for (int base = 0; base <= deg; base += CHUNK) {
        int len = min(CHUNK, deg + 1 - base);
        for (int i = tid; i < len; i += T) {
            int s = (base + i == deg) ? n : esrc[start + base + i];
            sidx[i] = s;
#pragma unroll
            for (int h = 0; h < HEADS; h++) {
                float e = ssrc[s * HEADS + h] + sd[h];
                e = e > 0.f ? e : 0.2f * e;
                sp[i][h] = __expf(e - mAll[h]);
            }
        }
        __syncthreads();
        for (int j = 0; j < len; j++) {
            float p = sp[j][head];
            z += p;
            int s = sidx[j];
            const uint2 raw = *(const uint2*)(hlin + (size_t)s * (HEADS * 128) + head * 128 + lane * 4);
            __half2 h0 = *(const __half2*)&raw.x;
            __half2 h1 = *(const __half2*)&raw.y;
            float2 f0 = __half22float2(h0);
            float2 f1 = __half22float2(h1);
            acc.x += p * f0.x;
            acc.y += p * f0.y;
            acc.z += p * f1.x;
            acc.w += p * f1.y;
        }
        __syncthreads();
    }

    float inv = 1.f / (z + 1e-16f);
    acc.x *= inv; acc.y *= inv; acc.z *= inv; acc.w *= inv;

    if (HEADS == 1) {
        float v[4] = {acc.x, acc.y, acc.z, acc.w};
#pragma unroll
        for (int k = 0; k < 4; k++) {
            int c = lane * 4 + k;
            outf[(size_t)n * 128 + c] = v[k] + bias[c];
        }
    } else {
        __shared__ float hb[HEADS * 128];
        *(float4*)&hb[head * 128 + lane * 4] = acc;
        __syncthreads();
        if (tid < 32) {
            float v[4];
#pragma unroll
            for (int k = 0; k < 4; k++) {
                int c = tid * 4 + k;
                float s = 0.f;
#pragma unroll
                for (int h = 0; h < HEADS; h++) s += hb[h * 128 + c];
                float w = s * (1.f / HEADS) + bias[c];
                if (ELUBN) {
                    w = w > 0.f ? w : (__expf(w) - 1.f);                       // ELU
                    w = (w - rm[c]) * rsqrtf(rv[c] + 1e-5f) * gam[c] + bet[c]; // BN eval
                }
                v[k] = w;
            }
            __half2 o[2] = {__floats2half2_rn(v[0], v[1]), __floats2half2_rn(v[2], v[3])};
            *(uint2*)(outh + (size_t)n * 128 + tid * 4) = *(uint2*)o;
        }
    }
}

// ---------------- pooling ----------------
__global__ void pool_partial(const float* __restrict__ f, const int* __restrict__ batch,
                             float* __restrict__ tot, float* __restrict__ cnt)
{
    int n0 = blockIdx.x * 256;
    int c = threadIdx.x;
    if (n0 >= NN) return;
    int cur = batch[n0];
    float acc = 0.f;
    int lc = 0;
    for (int i = 0; i < 256; i++) {
        int n = n0 + i;
        if (n >= NN) break;
        int g = batch[n];
        if (g != cur) {
            atomicAdd(&tot[cur * 128 + c], acc);
            if (c == 0) atomicAdd(&cnt[cur], (float)lc);
            acc = 0.f; lc = 0; cur = g;
        }
        acc += f[(size_t)n * 128 + c];
        lc++;
    }
    if (lc) {
        atomicAdd(&tot[cur * 128 + c], acc);
        if (c == 0) atomicAdd(&cnt[cur], (float)lc);
    }
}

__global__ void pool_final(const float* __restrict__ tot, const float* __restrict__ cnt,
                           float* __restrict__ out)
{
    int g = blockIdx.x, c = threadIdx.x;
    out[g * 128 + c] = tot[g * 128 + c] / fmaxf(cnt[g], 1.f);
}

// ---------------- host orchestration ----------------
extern "C" void kernel_launch(void* const* d_in, const int* in_sizes, int n_in,
                              void* d_out, int out_size)
{
    const float* x    = (const float*)d_in[0];
    const int*   src  = (const int*)d_in[1];
    const int*   dst  = (const int*)d_in[2];
    const int*   batch= (const int*)d_in[3];
    const float* W1   = (const float*)d_in[4];
    const float* as1  = (const float*)d_in[5];
    const float* ad1  = (const float*)d_in[6];
    const float* b1   = (const float*)d_in[7];
    const float* gm1  = (const float*)d_in[8];
    const float* be1  = (const float*)d_in[9];
    const float* m1   = (const float*)d_in[10];
    const float* v1   = (const float*)d_in[11];
    const float* W2   = (const float*)d_in[12];
    const float* as2  = (const float*)d_in[13];
    const float* ad2  = (const float*)d_in[14];
    const float* b2   = (const float*)d_in[15];
    const float* gm2  = (const float*)d_in[16];
    const float* be2  = (const float*)d_in[17];
    const float* m2   = (const float*)d_in[18];
    const float* v2   = (const float*)d_in[19];
    const float* W3   = (const float*)d_in[20];
    const float* as3  = (const float*)d_in[21];
    const float* ad3  = (const float*)d_in[22];
    const float* b3   = (const float*)d_in[23];

    __half *hlinh, *xh, *w1h, *w2h, *w3h, *f1h, *f2h;
    float *f3, *ssrc, *sdst, *tot, *cnt;
    int *rowptr, *cursor, *deg, *esrc, *bsums;
    cudaGetSymbolAddress((void**)&hlinh, g_hlinh);
    cudaGetSymbolAddress((void**)&xh,    g_xh);
    cudaGetSymbolAddress((void**)&w1h,   g_w1h);
    cudaGetSymbolAddress((void**)&w2h,   g_w2h);
    cudaGetSymbolAddress((void**)&w3h,   g_w3h);
    cudaGetSymbolAddress((void**)&f1h,   g_f1h);
    cudaGetSymbolAddress((void**)&f2h,   g_f2h);
    cudaGetSymbolAddress((void**)&f3,    g_f3);
    cudaGetSymbolAddress((void**)&ssrc,  g_ssrc);
    cudaGetSymbolAddress((void**)&sdst,  g_sdst);
    cudaGetSymbolAddress((void**)&rowptr,g_rowptr);
    cudaGetSymbolAddress((void**)&cursor,g_cursor);
    cudaGetSymbolAddress((void**)&deg,   g_deg);
    cudaGetSymbolAddress((void**)&esrc,  g_esrc);
    cudaGetSymbolAddress((void**)&bsums, g_bsums);
    cudaGetSymbolAddress((void**)&tot,   g_tot);
    cudaGetSymbolAddress((void**)&cnt,   g_cnt);

    static cudaStream_t sB = nullptr, sC = nullptr;
    static cudaEvent_t evFork = nullptr, evB = nullptr, evC1 = nullptr, evC2 = nullptr;
    if (!sB) {
        cudaStreamCreateWithFlags(&sB, cudaStreamNonBlocking);
        cudaStreamCreateWithFlags(&sC, cudaStreamNonBlocking);
        cudaEventCreateWithFlags(&evFork, cudaEventDisableTiming);
        cudaEventCreateWithFlags(&evB, cudaEventDisableTiming);
        cudaEventCreateWithFlags(&evC1, cudaEventDisableTiming);
        cudaEventCreateWithFlags(&evC2, cudaEventDisableTiming);
    }

    const int MB = (NN + 127) / 128;  // 313

    // ---- fork ----
    cudaEventRecord(evFork, 0);
    cudaStreamWaitEvent(sB, evFork, 0);
    cudaStreamWaitEvent(sC, evFork, 0);

    // ---- stream B: CSR build ----
    kzero_i<<<(NN + 255) / 256, 256, 0, sB>>>(deg, NN);
    hist_k<<<(EE + 255) / 256, 256, 0, sB>>>(dst, deg);
    scan_block<<<(NN + 1023) / 1024, 1024, 0, sB>>>(deg, rowptr, bsums, NN);
    scan_sums<<<1, 32, 0, sB>>>(bsums, (NN + 1023) / 1024);
    scan_add<<<(NN + 255) / 256, 256, 0, sB>>>(rowptr, cursor, bsums, NN);
    scatter_k<<<(EE + 255) / 256, 256, 0, sB>>>(src, dst, cursor, esrc);
    cudaEventRecord(evB, sB);

    // ---- stream C: weight conversions + pool zeroing ----
    conv_half<<<(DIN * 512 / 8 + 255) / 256, 256, 0, sC>>>(W1, w1h, DIN * 512 / 8);
    cudaEventRecord(evC1, sC);
    conv_half<<<(128 * 512 / 8 + 255) / 256, 256, 0, sC>>>(W2, w2h, 128 * 512 / 8);
    conv_half<<<(128 * 128 / 8 + 255) / 256, 256, 0, sC>>>(W3, w3h, 128 * 128 / 8);
    kzero_pool<<<(GG * 128 + 255) / 256, 256, 0, sC>>>(tot, cnt);
    cudaEventRecord(evC2, sC);

    // ---- main stream ----
    conv_half<<<(NN * DIN / 8 + 255) / 256, 256>>>(x, xh, NN * DIN / 8);
    cudaStreamWaitEvent(0, evC1, 0);
    gemm_h<<<dim3(4, MB), 256>>>(NN, 256, 512, xh, w1h, hlinh, 4, as1, ad1, ssrc, sdst);
    cudaStreamWaitEvent(0, evB, 0);
    gat_agg<4, true><<<NN, 128>>>(hlinh, ssrc, sdst, rowptr, esrc, b1, gm1, be1, m1, v1, f1h, nullptr);

    cudaStreamWaitEvent(0, evC2, 0);
    gemm_h<<<dim3(4, MB), 256>>>(NN, 128, 512, f1h, w2h, hlinh, 4, as2, ad2, ssrc, sdst);
    gat_agg<4, true><<<NN, 128>>>(hlinh, ssrc, sdst, rowptr, esrc, b2, gm2, be2, m2, v2, f2h, nullptr);

    gemm_h<<<dim3(1, MB), 256>>>(NN, 128, 128, f2h, w3h, hlinh, 1, as3, ad3, ssrc, sdst);
    gat_agg<1, false><<<NN, 32>>>(hlinh, ssrc, sdst, rowptr, esrc, b3,
                                  nullptr, nullptr, nullptr, nullptr, nullptr, f3);

    // ---- global mean pool ----
    pool_partial<<<(NN + 255) / 256, 128>>>(f3, batch, tot, cnt);
    pool_final<<<GG, 128>>>(tot, cnt, (float*)d_out);
}